// round 2
// baseline (speedup 1.0000x reference)
#include <cuda_runtime.h>
#include <cuda_bf16.h>

#define NEGV (-1e30f)

// ---------------- scratch (no allocations allowed) ----------------
__device__ float g_pooled[256 * 2048];
__device__ float g_f1[256 * 200];
__device__ float g_f2[256 * 200];

// ---------------- Kernel 1: ROI adaptive 2x2 max pool ----------------
// grid = 256 (one block per proposal), block = 256 threads (2 channels each)
__global__ void roipool_kernel(const float* __restrict__ fm,
                               const int* __restrict__ coords) {
    const int p = blockIdx.x;
    const int tid = threadIdx.x;

    const int y0 = coords[p * 4 + 0];
    const int x0 = coords[p * 4 + 1];
    const int y1 = coords[p * 4 + 2];
    const int x1 = coords[p * 4 + 3];

    const int sy = min(y0 / 8, 74);
    const int sx = min(x0 / 8, 126);
    const int ey = (y1 + 7) / 8;
    const int ex = (x1 + 7) / 8;
    const int h = max(ey - sy, 2);
    const int w = max(ex - sx, 2);

    // adaptive 2-bin boundaries (within 24-row/col crop window)
    const int e0r = (h + 1) / 2;   // bin0 rows: [0, e0r)
    const int s1r = h / 2;         // bin1 rows: [s1r, h)
    const int e0c = (w + 1) / 2;
    const int s1c = w / 2;
    const int rmax = min(h, 24);
    const int cmax = min(w, 24);

    float m00a = NEGV, m01a = NEGV, m10a = NEGV, m11a = NEGV;
    float m00b = NEGV, m01b = NEGV, m10b = NEGV, m11b = NEGV;

    for (int r = 0; r < rmax; r++) {
        const int gy = sy + r;
        const bool b0r = (r < e0r);
        const bool b1r = (r >= s1r);
        const bool rowv = (gy < 76);
        for (int c = 0; c < cmax; c++) {
            const int gx = sx + c;
            const bool valid = rowv && (gx < 128);
            float v0 = 0.0f, v1 = 0.0f;
            if (valid) {
                const float* base = fm + ((size_t)(gy * 128 + gx)) * 512;
                v0 = base[tid];
                v1 = base[tid + 256];
            }
            const bool b0c = (c < e0c);
            const bool b1c = (c >= s1c);
            if (b0r && b0c) { m00a = fmaxf(m00a, v0); m00b = fmaxf(m00b, v1); }
            if (b0r && b1c) { m01a = fmaxf(m01a, v0); m01b = fmaxf(m01b, v1); }
            if (b1r && b0c) { m10a = fmaxf(m10a, v0); m10b = fmaxf(m10b, v1); }
            if (b1r && b1c) { m11a = fmaxf(m11a, v0); m11b = fmaxf(m11b, v1); }
        }
    }

    float* outp = g_pooled + (size_t)p * 2048;
    // flatten order: (rb, cb, ch) -> (rb*2+cb)*512 + ch
    outp[0 * 512 + tid] = m00a;       outp[0 * 512 + tid + 256] = m00b;
    outp[1 * 512 + tid] = m01a;       outp[1 * 512 + tid + 256] = m01b;
    outp[2 * 512 + tid] = m10a;       outp[2 * 512 + tid + 256] = m10b;
    outp[3 * 512 + tid] = m11a;       outp[3 * 512 + tid + 256] = m11b;
}

// ---------------- Kernel 2/3: GEMM + bias + optional ReLU ----------------
// C[M,N] = act(A[M,K] @ B[K,N] + bias)
// BM=16, BN=40, BK=64, 160 threads, each thread: 4 rows x 1 col
__global__ void gemm_bias_relu(const float* __restrict__ A,
                               const float* __restrict__ B,
                               const float* __restrict__ bias,
                               float* __restrict__ C,
                               int M, int N, int K, int do_relu) {
    __shared__ float As[16][64];
    __shared__ float Bs[64][40];

    const int tid = threadIdx.x;
    const int j = tid % 40;     // col in tile
    const int rg = tid / 40;    // row group 0..3

    const int m0 = blockIdx.y * 16;
    const int n0 = blockIdx.x * 40;

    float acc0 = 0.f, acc1 = 0.f, acc2 = 0.f, acc3 = 0.f;

    for (int k0 = 0; k0 < K; k0 += 64) {
        // load A tile (16x64)
        for (int idx = tid; idx < 16 * 64; idx += 160) {
            const int r = idx >> 6;
            const int k = idx & 63;
            As[r][k] = (k0 + k < K) ? A[(size_t)(m0 + r) * K + k0 + k] : 0.0f;
        }
        // load B tile (64x40)
        for (int idx = tid; idx < 64 * 40; idx += 160) {
            const int kk = idx / 40;
            const int jj = idx % 40;
            Bs[kk][jj] = (k0 + kk < K) ? B[(size_t)(k0 + kk) * N + n0 + jj] : 0.0f;
        }
        __syncthreads();

        #pragma unroll 8
        for (int kk = 0; kk < 64; kk++) {
            const float bv = Bs[kk][j];
            acc0 = fmaf(As[rg * 4 + 0][kk], bv, acc0);
            acc1 = fmaf(As[rg * 4 + 1][kk], bv, acc1);
            acc2 = fmaf(As[rg * 4 + 2][kk], bv, acc2);
            acc3 = fmaf(As[rg * 4 + 3][kk], bv, acc3);
        }
        __syncthreads();
    }

    const float bj = bias[n0 + j];
    float v0 = acc0 + bj, v1 = acc1 + bj, v2 = acc2 + bj, v3 = acc3 + bj;
    if (do_relu) {
        v0 = fmaxf(v0, 0.f); v1 = fmaxf(v1, 0.f);
        v2 = fmaxf(v2, 0.f); v3 = fmaxf(v3, 0.f);
    }
    C[(size_t)(m0 + rg * 4 + 0) * N + n0 + j] = v0;
    C[(size_t)(m0 + rg * 4 + 1) * N + n0 + j] = v1;
    C[(size_t)(m0 + rg * 4 + 2) * N + n0 + j] = v2;
    C[(size_t)(m0 + rg * 4 + 3) * N + n0 + j] = v3;
}

// ---------------- Kernel 4: heads + softmax + box decode ----------------
// grid = 256, block = 64 threads
__global__ void head_kernel(const int* __restrict__ coords,
                            const float* __restrict__ W3,
                            const float* __restrict__ b3,
                            const float* __restrict__ W4,
                            const float* __restrict__ b4,
                            float* __restrict__ out) {
    __shared__ float f[200];
    __shared__ float o[21];   // 16 reg + 5 cls
    const int p = blockIdx.x;
    const int tid = threadIdx.x;

    for (int i = tid; i < 200; i += 64) f[i] = g_f2[(size_t)p * 200 + i];
    __syncthreads();

    if (tid < 16) {
        float s = b3[tid];
        #pragma unroll 4
        for (int k = 0; k < 200; k++) s = fmaf(f[k], W3[k * 16 + tid], s);
        o[tid] = s;
    } else if (tid < 21) {
        const int c = tid - 16;
        float s = b4[c];
        #pragma unroll 4
        for (int k = 0; k < 200; k++) s = fmaf(f[k], W4[k * 5 + c], s);
        o[tid] = s;
    }
    __syncthreads();

    if (tid == 0) {
        float l0 = o[16], l1 = o[17], l2 = o[18], l3 = o[19], l4 = o[20];
        // argmax (first max wins)
        int cls = 0;
        float best = l0;
        if (l1 > best) { best = l1; cls = 1; }
        if (l2 > best) { best = l2; cls = 2; }
        if (l3 > best) { best = l3; cls = 3; }
        if (l4 > best) { best = l4; cls = 4; }
        // softmax (max-subtracted like jax.nn.softmax)
        const float mx = best;
        const float e0 = expf(l0 - mx), e1 = expf(l1 - mx), e2 = expf(l2 - mx),
                    e3 = expf(l3 - mx), e4 = expf(l4 - mx);
        const float sum = e0 + e1 + e2 + e3 + e4;
        const float score = fmaxf(fmaxf(e1, e2), fmaxf(e3, e4)) / sum;

        const int j = max(cls - 1, 0);
        const float r0 = o[j * 4 + 0];
        const float r1 = o[j * 4 + 1];
        const float r2 = o[j * 4 + 2];
        const float r3 = o[j * 4 + 3];

        const float y0 = (float)coords[p * 4 + 0];
        const float x0 = (float)coords[p * 4 + 1];
        const float y1 = (float)coords[p * 4 + 2];
        const float x1 = (float)coords[p * 4 + 3];
        const float ph = y1 - y0;
        const float pw = x1 - x0;
        const float py = y0 + 0.5f * ph;
        const float px = x0 + 0.5f * pw;

        const float p_y = fmaf(ph, r0, py);
        const float p_x = fmaf(pw, r1, px);
        const float p_h = ph * fminf(fmaxf(expf(r2), 0.001f), 20.0f);
        const float p_w = pw * fminf(fmaxf(expf(r3), 0.001f), 20.0f);

        out[p * 4 + 0] = p_y;
        out[p * 4 + 1] = p_x;
        out[p * 4 + 2] = p_h;
        out[p * 4 + 3] = p_w;
        out[1024 + p] = score;
        out[1280 + p] = (cls != 0) ? 1.0f : 0.0f;
    }
}

// ---------------- launch ----------------
extern "C" void kernel_launch(void* const* d_in, const int* in_sizes, int n_in,
                              void* d_out, int out_size) {
    const float* fm     = (const float*)d_in[0];
    const int*   coords = (const int*)d_in[1];
    const float* W1 = (const float*)d_in[2];
    const float* b1 = (const float*)d_in[3];
    const float* W2 = (const float*)d_in[4];
    const float* b2 = (const float*)d_in[5];
    const float* W3 = (const float*)d_in[6];
    const float* b3 = (const float*)d_in[7];
    const float* W4 = (const float*)d_in[8];
    const float* b4 = (const float*)d_in[9];
    float* out = (float*)d_out;

    float* pooled = nullptr;
    float* f1 = nullptr;
    float* f2 = nullptr;
    cudaGetSymbolAddress((void**)&pooled, g_pooled);
    cudaGetSymbolAddress((void**)&f1, g_f1);
    cudaGetSymbolAddress((void**)&f2, g_f2);

    roipool_kernel<<<256, 256>>>(fm, coords);

    // FC1: [256,2048] @ [2048,200] + b1, relu
    gemm_bias_relu<<<dim3(5, 16), 160>>>(pooled, W1, b1, f1, 256, 200, 2048, 1);
    // FC2: [256,200] @ [200,200] + b2, relu
    gemm_bias_relu<<<dim3(5, 16), 160>>>(f1, W2, b2, f2, 256, 200, 200, 1);

    head_kernel<<<256, 64>>>(coords, W3, b3, W4, b4, out);
}

// round 4
// speedup vs baseline: 5.6204x; 5.6204x over previous
#include <cuda_runtime.h>
#include <cuda_bf16.h>

#define NEGV (-1e30f)

// ---------------- scratch (no allocations allowed) ----------------
__device__ float g_pooled[256 * 2048];
__device__ float g_part1[8 * 256 * 200];   // FC1 split-K partials
__device__ float g_f1[256 * 200];
__device__ float g_f2[256 * 200];

__device__ __forceinline__ float2 fmax2(float2 a, float2 b) {
    return make_float2(fmaxf(a.x, b.x), fmaxf(a.y, b.y));
}

// ---------------- Kernel 1: ROI adaptive 2x2 max pool ----------------
// grid = 256 (one block per proposal), block = 256 threads (float2 channels)
__global__ void roipool_kernel(const float* __restrict__ fm,
                               const int* __restrict__ coords) {
    const int p = blockIdx.x;
    const int tid = threadIdx.x;

    const int y0 = coords[p * 4 + 0];
    const int x0 = coords[p * 4 + 1];
    const int y1 = coords[p * 4 + 2];
    const int x1 = coords[p * 4 + 3];

    const int sy = min(y0 / 8, 74);
    const int sx = min(x0 / 8, 126);
    const int ey = (y1 + 7) / 8;
    const int ex = (x1 + 7) / 8;
    const int h = max(ey - sy, 2);
    const int w = max(ex - sx, 2);

    const int e0r = (h + 1) / 2;   // bin0 rows: [0, e0r)
    const int s1r = h / 2;         // bin1 rows: [s1r, h)
    const int e0c = (w + 1) / 2;
    const int s1c = w / 2;
    const int rmax = min(h, 24);
    const int cmax = min(w, 24);
    const int climit = min(cmax, 128 - sx);   // columns with in-bounds gx

    float2 m00 = make_float2(NEGV, NEGV), m01 = m00, m10 = m00, m11 = m00;

    for (int r = 0; r < rmax; r++) {
        const int gy = sy + r;
        const bool rowv = (gy < 76);
        const float* rowbase = fm + ((size_t)(gy * 128 + sx)) * 512 + 2 * tid;

        float2 c0 = make_float2(NEGV, NEGV);
        float2 c1 = make_float2(NEGV, NEGV);

        #pragma unroll 4
        for (int c = 0; c < cmax; c++) {
            float2 v = make_float2(0.0f, 0.0f);
            if (rowv && c < climit) {
                v = *reinterpret_cast<const float2*>(rowbase + (size_t)c * 512);
            }
            if (c < e0c)  c0 = fmax2(c0, v);
            if (c >= s1c) c1 = fmax2(c1, v);
        }
        if (r < e0r)  { m00 = fmax2(m00, c0); m01 = fmax2(m01, c1); }
        if (r >= s1r) { m10 = fmax2(m10, c0); m11 = fmax2(m11, c1); }
    }

    float* outp = g_pooled + (size_t)p * 2048 + 2 * tid;
    *reinterpret_cast<float2*>(outp + 0 * 512) = m00;
    *reinterpret_cast<float2*>(outp + 1 * 512) = m01;
    *reinterpret_cast<float2*>(outp + 2 * 512) = m10;
    *reinterpret_cast<float2*>(outp + 3 * 512) = m11;
}

// ---------------- Kernel 2: FC1 split-K partial GEMM ----------------
// A = pooled [256,2048], B = W1 [2048,200]
// grid = (32 mtiles of 8 rows, 8 K-splits of 256), block = 200 threads
__global__ void fc1_partial(const float* __restrict__ A,
                            const float* __restrict__ B,
                            float* __restrict__ part) {
    __shared__ float As[8][256];
    const int mt = blockIdx.x;
    const int ks = blockIdx.y;
    const int tid = threadIdx.x;
    const int m0 = mt * 8;
    const int k0 = ks * 256;

    for (int idx = tid; idx < 8 * 256; idx += 200) {
        const int r = idx >> 8;
        const int k = idx & 255;
        As[r][k] = A[(size_t)(m0 + r) * 2048 + k0 + k];
    }
    __syncthreads();

    const int j = tid;
    float acc[8];
    #pragma unroll
    for (int r = 0; r < 8; r++) acc[r] = 0.0f;

    const float* Bp = B + (size_t)k0 * 200 + j;
    #pragma unroll 2
    for (int k = 0; k < 256; k += 4) {
        const float b0 = Bp[(size_t)(k + 0) * 200];
        const float b1 = Bp[(size_t)(k + 1) * 200];
        const float b2 = Bp[(size_t)(k + 2) * 200];
        const float b3 = Bp[(size_t)(k + 3) * 200];
        #pragma unroll
        for (int r = 0; r < 8; r++) {
            const float4 a = *reinterpret_cast<const float4*>(&As[r][k]);
            acc[r] = fmaf(a.x, b0, acc[r]);
            acc[r] = fmaf(a.y, b1, acc[r]);
            acc[r] = fmaf(a.z, b2, acc[r]);
            acc[r] = fmaf(a.w, b3, acc[r]);
        }
    }

    float* out = part + ((size_t)ks * 256 + m0) * 200 + j;
    #pragma unroll
    for (int r = 0; r < 8; r++) out[(size_t)r * 200] = acc[r];
}

// ---------------- Kernel 3: split-K reduce + bias + ReLU ----------------
// grid = 200 blocks x 256 threads -> 51200 elements
__global__ void fc1_reduce(const float* __restrict__ part,
                           const float* __restrict__ bias,
                           float* __restrict__ out) {
    const int idx = blockIdx.x * 256 + threadIdx.x;
    const int j = idx % 200;
    float s = bias[j];
    #pragma unroll
    for (int ks = 0; ks < 8; ks++) s += part[(size_t)ks * 51200 + idx];
    out[idx] = fmaxf(s, 0.0f);
}

// ---------------- Kernel 4: FC2 (single-pass) ----------------
// A = f1 [256,200], B = W2 [200,200]; grid = 128 blocks (2 rows each), 200 thr
__global__ void fc2_kernel(const float* __restrict__ A,
                           const float* __restrict__ B,
                           const float* __restrict__ bias,
                           float* __restrict__ C) {
    __shared__ float As[2][200];
    const int m0 = blockIdx.x * 2;
    const int tid = threadIdx.x;

    As[0][tid] = A[(size_t)m0 * 200 + tid];
    As[1][tid] = A[(size_t)(m0 + 1) * 200 + tid];
    __syncthreads();

    const int j = tid;
    float acc0 = 0.f, acc1 = 0.f;
    #pragma unroll 2
    for (int k = 0; k < 200; k += 4) {
        const float b0 = B[(size_t)(k + 0) * 200 + j];
        const float b1 = B[(size_t)(k + 1) * 200 + j];
        const float b2 = B[(size_t)(k + 2) * 200 + j];
        const float b3 = B[(size_t)(k + 3) * 200 + j];
        const float4 a0 = *reinterpret_cast<const float4*>(&As[0][k]);
        const float4 a1 = *reinterpret_cast<const float4*>(&As[1][k]);
        acc0 = fmaf(a0.x, b0, acc0); acc0 = fmaf(a0.y, b1, acc0);
        acc0 = fmaf(a0.z, b2, acc0); acc0 = fmaf(a0.w, b3, acc0);
        acc1 = fmaf(a1.x, b0, acc1); acc1 = fmaf(a1.y, b1, acc1);
        acc1 = fmaf(a1.z, b2, acc1); acc1 = fmaf(a1.w, b3, acc1);
    }
    const float bj = bias[j];
    C[(size_t)m0 * 200 + j]       = fmaxf(acc0 + bj, 0.0f);
    C[(size_t)(m0 + 1) * 200 + j] = fmaxf(acc1 + bj, 0.0f);
}

// ---------------- Kernel 5: heads + softmax + box decode ----------------
// grid = 32 blocks (8 proposals each), block = 256 threads
__global__ void head_kernel(const int* __restrict__ coords,
                            const float* __restrict__ W3,
                            const float* __restrict__ b3,
                            const float* __restrict__ W4,
                            const float* __restrict__ b4,
                            const float* __restrict__ f2,
                            float* __restrict__ out) {
    __shared__ float fs[8][200];
    __shared__ float wk[200 * 21];
    __shared__ float os[8][21];
    const int pb = blockIdx.x * 8;
    const int tid = threadIdx.x;

    for (int idx = tid; idx < 8 * 200; idx += 256)
        fs[idx / 200][idx % 200] = f2[(size_t)pb * 200 + idx];
    for (int idx = tid; idx < 200 * 16; idx += 256) {
        const int k = idx / 16, o = idx % 16;
        wk[k * 21 + o] = W3[idx];
    }
    for (int idx = tid; idx < 200 * 5; idx += 256) {
        const int k = idx / 5, c = idx % 5;
        wk[k * 21 + 16 + c] = W4[idx];
    }
    __syncthreads();

    if (tid < 168) {
        const int prop = tid / 21;
        const int o = tid % 21;
        float s0 = (o < 16) ? b3[o] : b4[o - 16];
        float s1 = 0.f, s2 = 0.f, s3 = 0.f;
        #pragma unroll 2
        for (int k = 0; k < 200; k += 4) {
            s0 = fmaf(fs[prop][k + 0], wk[(k + 0) * 21 + o], s0);
            s1 = fmaf(fs[prop][k + 1], wk[(k + 1) * 21 + o], s1);
            s2 = fmaf(fs[prop][k + 2], wk[(k + 2) * 21 + o], s2);
            s3 = fmaf(fs[prop][k + 3], wk[(k + 3) * 21 + o], s3);
        }
        os[prop][o] = (s0 + s1) + (s2 + s3);
    }
    __syncthreads();

    if (tid < 8) {
        const int p = pb + tid;
        const float l0 = os[tid][16], l1 = os[tid][17], l2 = os[tid][18],
                    l3 = os[tid][19], l4 = os[tid][20];
        int cls = 0;
        float best = l0;
        if (l1 > best) { best = l1; cls = 1; }
        if (l2 > best) { best = l2; cls = 2; }
        if (l3 > best) { best = l3; cls = 3; }
        if (l4 > best) { best = l4; cls = 4; }
        const float mx = best;
        const float e0 = expf(l0 - mx), e1 = expf(l1 - mx), e2 = expf(l2 - mx),
                    e3 = expf(l3 - mx), e4 = expf(l4 - mx);
        const float sum = e0 + e1 + e2 + e3 + e4;
        const float score = fmaxf(fmaxf(e1, e2), fmaxf(e3, e4)) / sum;

        const int jj = max(cls - 1, 0);
        const float r0 = os[tid][jj * 4 + 0];
        const float r1 = os[tid][jj * 4 + 1];
        const float r2 = os[tid][jj * 4 + 2];
        const float r3 = os[tid][jj * 4 + 3];

        const float y0 = (float)coords[p * 4 + 0];
        const float x0 = (float)coords[p * 4 + 1];
        const float y1 = (float)coords[p * 4 + 2];
        const float x1 = (float)coords[p * 4 + 3];
        const float ph = y1 - y0;
        const float pw = x1 - x0;
        const float py = y0 + 0.5f * ph;
        const float px = x0 + 0.5f * pw;

        out[p * 4 + 0] = fmaf(ph, r0, py);
        out[p * 4 + 1] = fmaf(pw, r1, px);
        out[p * 4 + 2] = ph * fminf(fmaxf(expf(r2), 0.001f), 20.0f);
        out[p * 4 + 3] = pw * fminf(fmaxf(expf(r3), 0.001f), 20.0f);
        out[1024 + p] = score;
        out[1280 + p] = (cls != 0) ? 1.0f : 0.0f;
    }
}

// ---------------- launch ----------------
extern "C" void kernel_launch(void* const* d_in, const int* in_sizes, int n_in,
                              void* d_out, int out_size) {
    const float* fm     = (const float*)d_in[0];
    const int*   coords = (const int*)d_in[1];
    const float* W1 = (const float*)d_in[2];
    const float* b1 = (const float*)d_in[3];
    const float* W2 = (const float*)d_in[4];
    const float* b2 = (const float*)d_in[5];
    const float* W3 = (const float*)d_in[6];
    const float* b3 = (const float*)d_in[7];
    const float* W4 = (const float*)d_in[8];
    const float* b4 = (const float*)d_in[9];
    float* out = (float*)d_out;

    float *pooled = nullptr, *part1 = nullptr, *f1 = nullptr, *f2 = nullptr;
    cudaGetSymbolAddress((void**)&pooled, g_pooled);
    cudaGetSymbolAddress((void**)&part1, g_part1);
    cudaGetSymbolAddress((void**)&f1, g_f1);
    cudaGetSymbolAddress((void**)&f2, g_f2);

    roipool_kernel<<<256, 256>>>(fm, coords);
    fc1_partial<<<dim3(32, 8), 200>>>(pooled, W1, part1);
    fc1_reduce<<<200, 256>>>(part1, b1, f1);
    fc2_kernel<<<128, 200>>>(f1, W2, b2, f2);
    head_kernel<<<32, 256>>>(coords, W3, b3, W4, b4, f2, out);
}